// round 7
// baseline (speedup 1.0000x reference)
#include <cuda_runtime.h>
#include <cuda_fp16.h>
#include <cstdint>

// ---------------------------------------------------------------------------
// LinearAttention, fp16 mma.sync m16n8k16 (fp32 accum) + ldmatrix + cp.async.
// R7: all fragment ldmatrix for a BK=32 iteration hoisted ahead of the MMA
// stream (one exposed LDSM wavefront per iteration instead of two).
// ---------------------------------------------------------------------------

#define BDIM   8
#define CIN    256
#define NPIX   4096
#define HEADS  4
#define DIMH   128
#define HID    512
#define QKVR   1536
#define KSPLIT 8

#define SAH    40                 // A smem stride (halfs): 80B
#define SBH    136                // B smem stride (halfs): 272B
#define ASTGH  (128 * SAH)        // 5120 halfs = 10240 B
#define BSTGH  (32 * SBH)         // 4352 halfs = 8704 B
#define SMEM_NN (3 * (ASTGH + BSTGH) * 2)   // 56832
#define SMEM_NT (3 * 2 * ASTGH * 2)         // 61440

__device__ __half g_qkvh[(size_t)BDIM * QKVR * NPIX];
__device__ __half g_attnh[(size_t)BDIM * HID * NPIX];
__device__ float  g_ctx_part[KSPLIT][BDIM * HEADS][DIMH][DIMH];
__device__ __half g_ctxTh[BDIM * HEADS][DIMH][DIMH];
__device__ __half g_xh [(size_t)BDIM * CIN * NPIX];
__device__ __half g_wqh[QKVR * CIN];
__device__ __half g_woh[CIN * HID];

// ---------------- helpers ----------------
__device__ __forceinline__ void cpa16(uint32_t d, const void* s) {
    asm volatile("cp.async.cg.shared.global [%0], [%1], 16;\n" :: "r"(d), "l"(s));
}
__device__ __forceinline__ void cp_commit() { asm volatile("cp.async.commit_group;\n"); }
template<int N> __device__ __forceinline__ void cp_wait() {
    asm volatile("cp.async.wait_group %0;\n" :: "n"(N));
}
__device__ __forceinline__ void ldsm_x4(uint32_t r[4], uint32_t a) {
    asm volatile("ldmatrix.sync.aligned.m8n8.x4.shared.b16 {%0,%1,%2,%3}, [%4];"
        : "=r"(r[0]), "=r"(r[1]), "=r"(r[2]), "=r"(r[3]) : "r"(a));
}
__device__ __forceinline__ void ldsm_x4t(uint32_t r[4], uint32_t a) {
    asm volatile("ldmatrix.sync.aligned.m8n8.x4.trans.shared.b16 {%0,%1,%2,%3}, [%4];"
        : "=r"(r[0]), "=r"(r[1]), "=r"(r[2]), "=r"(r[3]) : "r"(a));
}
__device__ __forceinline__ void mma16(float c[4], const uint32_t a[4], const uint32_t b0, const uint32_t b1) {
    asm volatile(
        "mma.sync.aligned.m16n8k16.row.col.f32.f16.f16.f32 "
        "{%0,%1,%2,%3}, {%4,%5,%6,%7}, {%8,%9}, {%0,%1,%2,%3};"
        : "+f"(c[0]), "+f"(c[1]), "+f"(c[2]), "+f"(c[3])
        : "r"(a[0]), "r"(a[1]), "r"(a[2]), "r"(a[3]), "r"(b0), "r"(b1));
}

// ---------------------------------------------------------------------------
__global__ __launch_bounds__(256) void f2h(
    const float* __restrict__ in, __half* __restrict__ out, int n4)
{
    int i = blockIdx.x * 256 + threadIdx.x;
    if (i < n4) {
        float4 v = ((const float4*)in)[i];
        __half2 h0 = __floats2half2_rn(v.x, v.y);
        __half2 h1 = __floats2half2_rn(v.z, v.w);
        uint2 u;
        u.x = *(uint32_t*)&h0;
        u.y = *(uint32_t*)&h1;
        ((uint2*)out)[i] = u;
    }
}

// ---------------------------------------------------------------------------
// NN GEMM fp16: C = A[M,K]@B[K,N] (+bias). 128x128 tile, BK=32, 3-stage.
// ---------------------------------------------------------------------------
template<bool HALF_OUT>
__global__ __launch_bounds__(256, 2) void gemm_nn(
    const __half* __restrict__ A, long long sA1, long long sA2, int lda,
    const __half* __restrict__ B, long long sB1, long long sB2,
    void*         __restrict__ Cv, long long sC1, long long sC2,
    const float* __restrict__ bias,
    int zdiv, int N, int K)
{
    extern __shared__ __half sm[];
    __half* Asm = sm;                 // [3][128][SAH]
    __half* Bsm = sm + 3 * ASTGH;     // [3][32][SBH]

    const int bm = blockIdx.y, bn = blockIdx.x;
    const int zo = blockIdx.z / zdiv, zi = blockIdx.z % zdiv;
    A += zo * sA1 + zi * sA2;
    B += zo * sB1 + zi * sB2;

    const int tid  = threadIdx.x;
    const int lane = tid & 31, warp = tid >> 5;
    const int g    = lane >> 2, t4 = lane & 3;
    const int wm   = warp & 3,  wn = warp >> 2;
    const int l15  = lane & 15, lh = lane >> 4;

    const __half* Ag = A + (long long)bm * 128 * lda;
    const __half* Bg = B + bn * 128;

    const uint32_t asm0 = (uint32_t)__cvta_generic_to_shared(Asm);
    const uint32_t bsm0 = (uint32_t)__cvta_generic_to_shared(Bsm);

#define LD_NN(st, kk) do {                                                       \
    uint32_t ab = asm0 + (uint32_t)(st) * (ASTGH * 2);                           \
    uint32_t bb = bsm0 + (uint32_t)(st) * (BSTGH * 2);                           \
    _Pragma("unroll")                                                            \
    for (int t = 0; t < 2; t++) {                                                \
        int idx = t * 256 + tid;                                                 \
        int row = idx >> 2, ch = idx & 3;                                        \
        cpa16(ab + (uint32_t)(row * SAH + ch * 8) * 2,                           \
              Ag + (long long)row * lda + (kk) + ch * 8);                        \
        int kr = idx >> 4, nc = idx & 15;                                        \
        cpa16(bb + (uint32_t)(kr * SBH + nc * 8) * 2,                            \
              Bg + (long long)((kk) + kr) * N + nc * 8);                         \
    }                                                                            \
    cp_commit();                                                                 \
} while (0)

    float acc[2][8][4] = {};
    const int niter = K >> 5;

    LD_NN(0, 0);
    LD_NN(1, 32);

    for (int it = 0; it < niter; ++it) {
        cp_wait<1>();
        __syncthreads();
        const int ls = it + 2;
        if (ls < niter) { LD_NN(ls % 3, ls * 32); }
        else            { cp_commit(); }

        const uint32_t Asb = asm0 + (uint32_t)(it % 3) * (ASTGH * 2);
        const uint32_t Bsb = bsm0 + (uint32_t)(it % 3) * (BSTGH * 2);

        // hoisted fragment loads for BOTH k16 steps
        uint32_t af[2][2][4], bf[2][8][2];
#pragma unroll
        for (int h = 0; h < 2; h++) {
            const int k16 = h * 16;
#pragma unroll
            for (int im = 0; im < 2; im++) {
                int m = wm * 32 + im * 16 + l15;
                ldsm_x4(af[h][im], Asb + (uint32_t)(m * SAH + k16 + lh * 8) * 2);
            }
#pragma unroll
            for (int pr = 0; pr < 4; pr++) {
                int n0 = wn * 64 + pr * 16;
                uint32_t bq[4];
                ldsm_x4t(bq, Bsb + (uint32_t)((k16 + l15) * SBH + n0 + lh * 8) * 2);
                bf[h][2 * pr][0] = bq[0]; bf[h][2 * pr][1] = bq[1];
                bf[h][2 * pr + 1][0] = bq[2]; bf[h][2 * pr + 1][1] = bq[3];
            }
        }
#pragma unroll
        for (int h = 0; h < 2; h++)
#pragma unroll
            for (int im = 0; im < 2; im++)
#pragma unroll
                for (int in = 0; in < 8; in++)
                    mma16(acc[im][in], af[h][im], bf[h][in][0], bf[h][in][1]);
    }
#undef LD_NN

    if (HALF_OUT) {
        __half* C = (__half*)Cv + zo * sC1 + zi * sC2;
#pragma unroll
        for (int im = 0; im < 2; im++) {
            int m0 = bm * 128 + wm * 32 + im * 16 + g;
#pragma unroll
            for (int in = 0; in < 8; in++) {
                int n0 = bn * 128 + wn * 64 + in * 8 + t4 * 2;
                __half2 h0 = __floats2half2_rn(acc[im][in][0], acc[im][in][1]);
                __half2 h1 = __floats2half2_rn(acc[im][in][2], acc[im][in][3]);
                *(__half2*)(C + (long long)m0 * N + n0)       = h0;
                *(__half2*)(C + (long long)(m0 + 8) * N + n0) = h1;
            }
        }
    } else {
        float* C = (float*)Cv + zo * sC1 + zi * sC2;
#pragma unroll
        for (int im = 0; im < 2; im++) {
            int m0 = bm * 128 + wm * 32 + im * 16 + g;
            float bv0 = bias ? bias[m0]     : 0.f;
            float bv1 = bias ? bias[m0 + 8] : 0.f;
#pragma unroll
            for (int in = 0; in < 8; in++) {
                int n0 = bn * 128 + wn * 64 + in * 8 + t4 * 2;
                *(float2*)(C + (long long)m0 * N + n0) =
                    make_float2(acc[im][in][0] + bv0, acc[im][in][1] + bv0);
                *(float2*)(C + (long long)(m0 + 8) * N + n0) =
                    make_float2(acc[im][in][2] + bv1, acc[im][in][3] + bv1);
            }
        }
    }
}

// ---------------------------------------------------------------------------
// GEMM2 (NT, split-K): ctx_part[slice][bh][e][d] = sum_{n slice} v[e,n]k[d,n]
// ---------------------------------------------------------------------------
__global__ __launch_bounds__(256, 2) void gemm_nt_ctx()
{
    extern __shared__ __half sm[];
    __half* Asm = sm;                 // [3][128][SAH] (v: [e][k])
    __half* Bsm = sm + 3 * ASTGH;     // [3][128][SAH] (k: [d][k])

    const int slice = blockIdx.x;
    const int bh    = blockIdx.y;
    const int b = bh >> 2, h4 = bh & 3;

    const __half* Ag = g_qkvh + ((long long)b * QKVR + 1024 + h4 * 128) * NPIX;
    const __half* Bg = g_qkvh + ((long long)b * QKVR +  512 + h4 * 128) * NPIX;
    float* C = &g_ctx_part[slice][bh][0][0];

    const int tid  = threadIdx.x;
    const int lane = tid & 31, warp = tid >> 5;
    const int g    = lane >> 2, t4 = lane & 3;
    const int wm   = warp & 3,  wn = warp >> 2;
    const int l15  = lane & 15, lh = lane >> 4;

    const uint32_t asm0 = (uint32_t)__cvta_generic_to_shared(Asm);
    const uint32_t bsm0 = (uint32_t)__cvta_generic_to_shared(Bsm);

#define LD_NT(st, kk) do {                                                       \
    uint32_t ab = asm0 + (uint32_t)(st) * (ASTGH * 2);                           \
    uint32_t bb = bsm0 + (uint32_t)(st) * (ASTGH * 2);                           \
    _Pragma("unroll")                                                            \
    for (int t = 0; t < 2; t++) {                                                \
        int idx = t * 256 + tid;                                                 \
        int row = idx >> 2, ch = idx & 3;                                        \
        uint32_t so = (uint32_t)(row * SAH + ch * 8) * 2;                        \
        cpa16(ab + so, Ag + (long long)row * NPIX + (kk) + ch * 8);              \
        cpa16(bb + so, Bg + (long long)row * NPIX + (kk) + ch * 8);              \
    }                                                                            \
    cp_commit();                                                                 \
} while (0)

    float acc[2][8][4] = {};
    const int kbeg  = slice * (NPIX / KSPLIT);
    const int niter = (NPIX / KSPLIT) >> 5;   // 16

    LD_NT(0, kbeg);
    LD_NT(1, kbeg + 32);

    for (int it = 0; it < niter; ++it) {
        cp_wait<1>();
        __syncthreads();
        const int ls = it + 2;
        if (ls < niter) { LD_NT(ls % 3, kbeg + ls * 32); }
        else            { cp_commit(); }

        const uint32_t Asb = asm0 + (uint32_t)(it % 3) * (ASTGH * 2);
        const uint32_t Bsb = bsm0 + (uint32_t)(it % 3) * (ASTGH * 2);

        uint32_t af[2][2][4], bf[2][8][2];
#pragma unroll
        for (int h = 0; h < 2; h++) {
            const int k16 = h * 16;
#pragma unroll
            for (int im = 0; im < 2; im++) {
                int m = wm * 32 + im * 16 + l15;
                ldsm_x4(af[h][im], Asb + (uint32_t)(m * SAH + k16 + lh * 8) * 2);
            }
#pragma unroll
            for (int pr = 0; pr < 4; pr++) {
                int d0 = wn * 64 + pr * 16;
                uint32_t bq[4];
                ldsm_x4(bq, Bsb + (uint32_t)((d0 + l15) * SAH + k16 + lh * 8) * 2);
                bf[h][2 * pr][0] = bq[0]; bf[h][2 * pr][1] = bq[2];
                bf[h][2 * pr + 1][0] = bq[1]; bf[h][2 * pr + 1][1] = bq[3];
            }
        }
#pragma unroll
        for (int h = 0; h < 2; h++)
#pragma unroll
            for (int im = 0; im < 2; im++)
#pragma unroll
                for (int in = 0; in < 8; in++)
                    mma16(acc[im][in], af[h][im], bf[h][in][0], bf[h][in][1]);
    }
#undef LD_NT

#pragma unroll
    for (int im = 0; im < 2; im++) {
        int m0 = wm * 32 + im * 16 + g;
#pragma unroll
        for (int in = 0; in < 8; in++) {
            int n0 = wn * 64 + in * 8 + t4 * 2;
            *(float2*)(C + m0 * 128 + n0)       = make_float2(acc[im][in][0], acc[im][in][1]);
            *(float2*)(C + (m0 + 8) * 128 + n0) = make_float2(acc[im][in][2], acc[im][in][3]);
        }
    }
}

__global__ __launch_bounds__(256) void reduce_ctx()
{
    const long long i = (long long)blockIdx.x * 256 + threadIdx.x;
    const long long total = (long long)BDIM * HEADS * DIMH * DIMH;
    if (i >= total) return;
    const float* p = &g_ctx_part[0][0][0][0];
    float s = 0.f;
#pragma unroll
    for (int k = 0; k < KSPLIT; k++) s += p[(long long)k * total + i];
    (&g_ctxTh[0][0][0])[i] = __float2half_rn(s);
}

// ---------------------------------------------------------------------------
// Softmax over n (4096) on fp16 k rows; register-resident, fp32 math.
// ---------------------------------------------------------------------------
__global__ __launch_bounds__(256) void softmax_k()
{
    const int r = blockIdx.x;
    const int b = r >> 9;
    const int o = 512 + (r & 511);
    __half* row = g_qkvh + ((long long)b * QKVR + o) * NPIX;

    __shared__ float red[8];
    const int tid = threadIdx.x;

    uint4 u0 = ((const uint4*)row)[tid];
    uint4 u1 = ((const uint4*)row)[256 + tid];

    float v[16];
    {
        const __half2* h0 = (const __half2*)&u0;
        const __half2* h1 = (const __half2*)&u1;
#pragma unroll
        for (int i = 0; i < 4; i++) {
            float2 f0 = __half22float2(h0[i]);
            float2 f1 = __half22float2(h1[i]);
            v[2 * i] = f0.x; v[2 * i + 1] = f0.y;
            v[8 + 2 * i] = f1.x; v[8 + 2 * i + 1] = f1.y;
        }
    }

    float mx = v[0];
#pragma unroll
    for (int i = 1; i < 16; i++) mx = fmaxf(mx, v[i]);
#pragma unroll
    for (int off = 16; off; off >>= 1) mx = fmaxf(mx, __shfl_xor_sync(0xffffffffu, mx, off));
    if ((tid & 31) == 0) red[tid >> 5] = mx;
    __syncthreads();
    float m = red[0];
#pragma unroll
    for (int i = 1; i < 8; i++) m = fmaxf(m, red[i]);
    __syncthreads();

    float s = 0.f;
#pragma unroll
    for (int i = 0; i < 16; i++) { v[i] = __expf(v[i] - m); s += v[i]; }
#pragma unroll
    for (int off = 16; off; off >>= 1) s += __shfl_xor_sync(0xffffffffu, s, off);
    if ((tid & 31) == 0) red[tid >> 5] = s;
    __syncthreads();
    float tot = 0.f;
#pragma unroll
    for (int i = 0; i < 8; i++) tot += red[i];
    const float inv = 1.f / tot;

    uint4 w0, w1;
    __half2* o0 = (__half2*)&w0;
    __half2* o1 = (__half2*)&w1;
#pragma unroll
    for (int i = 0; i < 4; i++) {
        o0[i] = __floats2half2_rn(v[2 * i] * inv, v[2 * i + 1] * inv);
        o1[i] = __floats2half2_rn(v[8 + 2 * i] * inv, v[8 + 2 * i + 1] * inv);
    }
    ((uint4*)row)[tid] = w0;
    ((uint4*)row)[256 + tid] = w1;
}

// ---------------------------------------------------------------------------
extern "C" void kernel_launch(void* const* d_in, const int* in_sizes, int n_in,
                              void* d_out, int out_size)
{
    (void)in_sizes; (void)n_in; (void)out_size;
    const float* x     = (const float*)d_in[0];
    const float* w_qkv = (const float*)d_in[1];
    const float* w_out = (const float*)d_in[2];
    const float* b_out = (const float*)d_in[3];
    float* out = (float*)d_out;

    __half *qkv_p, *attn_p, *ctxT_p, *xh_p, *wq_p, *wo_p;
    cudaGetSymbolAddress((void**)&qkv_p,  g_qkvh);
    cudaGetSymbolAddress((void**)&attn_p, g_attnh);
    cudaGetSymbolAddress((void**)&ctxT_p, g_ctxTh);
    cudaGetSymbolAddress((void**)&xh_p,   g_xh);
    cudaGetSymbolAddress((void**)&wq_p,   g_wqh);
    cudaGetSymbolAddress((void**)&wo_p,   g_woh);

    cudaFuncSetAttribute((const void*)gemm_nn<true>,
                         cudaFuncAttributeMaxDynamicSharedMemorySize, SMEM_NN);
    cudaFuncSetAttribute((const void*)gemm_nn<false>,
                         cudaFuncAttributeMaxDynamicSharedMemorySize, SMEM_NN);
    cudaFuncSetAttribute((const void*)gemm_nt_ctx,
                         cudaFuncAttributeMaxDynamicSharedMemorySize, SMEM_NT);

    dim3 blk(256);

    f2h<<<(BDIM * CIN * NPIX / 4 + 255) / 256, blk>>>(x, xh_p, BDIM * CIN * NPIX / 4);
    f2h<<<(QKVR * CIN / 4 + 255) / 256, blk>>>(w_qkv, wq_p, QKVR * CIN / 4);
    f2h<<<(CIN * HID / 4 + 255) / 256, blk>>>(w_out, wo_p, CIN * HID / 4);

    // GEMM1: qkv[b] = w_qkv @ x[b]  -> fp16
    gemm_nn<true><<<dim3(NPIX / 128, QKVR / 128, BDIM), blk, SMEM_NN>>>(
        wq_p, 0, 0, CIN,
        xh_p, (long long)CIN * NPIX, 0,
        qkv_p, (long long)QKVR * NPIX, 0,
        nullptr, 1, NPIX, CIN);

    softmax_k<<<BDIM * HEADS * DIMH, blk>>>();

    gemm_nt_ctx<<<dim3(KSPLIT, BDIM * HEADS), blk, SMEM_NT>>>();
    reduce_ctx<<<(BDIM * HEADS * DIMH * DIMH) / 256, blk>>>();

    // GEMM3: attn[b,h] = ctxT[b,h] @ q[b,h]  -> fp16
    gemm_nn<true><<<dim3(NPIX / 128, 1, BDIM * HEADS), blk, SMEM_NN>>>(
        ctxT_p, (long long)HEADS * DIMH * DIMH, (long long)DIMH * DIMH, DIMH,
        qkv_p, (long long)QKVR * NPIX, (long long)DIMH * NPIX,
        attn_p, (long long)HID * NPIX, (long long)DIMH * NPIX,
        nullptr, HEADS, NPIX, DIMH);

    // GEMM4: out[b] = w_out @ attn[b] + b_out  -> fp32
    gemm_nn<false><<<dim3(NPIX / 128, CIN / 128, BDIM), blk, SMEM_NN>>>(
        wo_p, 0, 0, HID,
        attn_p, (long long)HID * NPIX, 0,
        out, (long long)CIN * NPIX, 0,
        b_out, 1, NPIX, HID);
}